// round 7
// baseline (speedup 1.0000x reference)
#include <cuda_runtime.h>
#include <cstdint>

#define NXQ 41
#define NXY 1681
#define GQ 68921
#define KPICK 4
#define NEGV (-1.0e9f)
#define VTH  (-1.0e8f)
#define NT 512
#define NWARP (NT/32)
#define NC 539               /* per-row 128-voxel chunks (shifted grid) */
#define CPW ((NC + NWARP - 1) / NWARP)   /* 34 chunks per warp, contiguous */
#define MW 2160              /* padded 32-bit mask words */

__device__ unsigned int g_maskw[MW];

// Sphere mask bitfield, bit-exact vs np.linalg.norm(grid_xyz) <= 6.0 in f32
// (monotone correctly-rounded sqrt => equivalent to ss <= 36.0f).
__global__ void build_mask_kernel(const float* __restrict__ grid_xyz) {
    int g = blockIdx.x * blockDim.x + threadIdx.x;
    bool inside = false;
    if (g < GQ) {
        float x = grid_xyz[3 * g + 0];
        float y = grid_xyz[3 * g + 1];
        float z = grid_xyz[3 * g + 2];
        float ss = __fadd_rn(__fadd_rn(__fmul_rn(x, x), __fmul_rn(y, y)), __fmul_rn(z, z));
        inside = (ss <= 36.0f);
    }
    unsigned int b = __ballot_sync(0xffffffffu, inside);
    if ((threadIdx.x & 31) == 0) {
        int w = g >> 5;
        if (w < MW) g_maskw[w] = b;
    }
}

// Order-preserving float<->uint maps
__device__ __forceinline__ unsigned f2ord(float f) {
    int u = __float_as_int(f);
    return (unsigned)(u ^ ((u >> 31) | 0x80000000));
}
__device__ __forceinline__ float ord2f(unsigned o) {
    int m = (~(int)o) >> 31;
    return __int_as_float((int)(o ^ (unsigned)(m | 0x80000000)));
}

__global__ __launch_bounds__(NT, 2) void peaks_kernel(
    const float* __restrict__ density,
    const float* __restrict__ grid_xyz,
    const float* __restrict__ Rmats,
    const float* __restrict__ tpos,
    const float* __restrict__ node_mask,
    float* __restrict__ out,
    int rows, int C)
{
    __shared__ unsigned int s_mw[MW];
    __shared__ unsigned int s_cord[NC];
    __shared__ unsigned char s_class[NC];   /* 0 empty, 1 partial/edge, 2 full */
    __shared__ unsigned char s_flag[NC];
    __shared__ float s_ax[NXQ];
    __shared__ unsigned s_wv[NWARP];
    __shared__ int      s_wi[NWARP];
    __shared__ int s_pi[KPICK], s_pj[KPICK], s_pk[KPICK], s_pv[KPICK];
    __shared__ float s_ps[KPICK];

    const int tid  = threadIdx.x;
    const int lane = tid & 31;
    const int warp = tid >> 5;
    const int row  = blockIdx.x;
    const int s    = (4 - (row & 3)) & 3;          // (row*GQ + s) % 4 == 0
    const float* __restrict__ d = density + (long long)row * GQ;
    const unsigned ORD_NEG = f2ord(NEGV);
    const unsigned ORD_VTH = f2ord(VTH);

    for (int i = tid; i < MW; i += NT) s_mw[i] = g_maskw[i];
    // classify chunks: 0 = all-outside, 2 = all-inside (non-edge), 1 = otherwise
    for (int c = tid; c < NC; c += NT) {
        int base = s + (c << 7);
        unsigned cls;
        if ((c == 0 && s != 0) || base + 128 > GQ) {
            cls = 1;
        } else {
            int w0 = base >> 5;
            unsigned o = 0, a = 0xFFFFFFFFu;
#pragma unroll
            for (int q = 0; q < 4; q++) {
                unsigned sw = __funnelshift_r(g_maskw[w0 + q], g_maskw[w0 + q + 1], s);
                o |= sw; a &= sw;
            }
            cls = (o == 0u) ? 0u : ((a == 0xFFFFFFFFu) ? 2u : 1u);
        }
        s_class[c] = (unsigned char)cls;
        s_cord[c] = ORD_NEG;
        s_flag[c] = 0;
    }
    if (tid < NXQ) s_ax[tid] = grid_xyz[(long long)tid * NXY * 3];
    __syncthreads();

    // ---- streaming pass: warp owns contiguous chunk range, 4 chunks in flight ----
    {
        const int cs = warp * CPW;
        const int ce = (cs + CPW < NC) ? cs + CPW : NC;
        for (int c0 = cs; c0 < ce; c0 += 4) {
            unsigned nib[4]; float4 a[4]; int cls[4];
#pragma unroll
            for (int u = 0; u < 4; u++) {
                int c = c0 + u;
                nib[u] = 0;
                cls[u] = 0;
                if (c < ce) {
                    cls[u] = s_class[c];
                    int g0 = s + (c << 7) + (lane << 2);
                    bool edge = (c == 0 && s != 0) || (s + (c << 7) + 128 > GQ);
                    if (cls[u] == 2) nib[u] = 0xFu;
                    else if (cls[u] == 1 && !edge) {
                        int w = g0 >> 5;
                        nib[u] = __funnelshift_r(s_mw[w], s_mw[w + 1], g0) & 0xFu;
                    }
                    if (nib[u])
                        a[u] = __ldg(reinterpret_cast<const float4*>(d + g0));
                    if (cls[u] == 1 && edge) nib[u] = 0x80000000u;   // edge marker
                }
            }
#pragma unroll
            for (int u = 0; u < 4; u++) {
                int c = c0 + u;
                if (c >= ce) break;
                float bv = NEGV;
                if (nib[u] == 0xFu) {
                    bv = fmaxf(fmaxf(a[u].x, a[u].y), fmaxf(a[u].z, a[u].w));
                } else if (nib[u] == 0x80000000u) {
                    int base = s + (c << 7);
                    int lo = (c == 0) ? 0 : base;
                    int hi = base + 128; if (hi > GQ) hi = GQ;
                    for (int g = lo + lane; g < hi; g += 32)
                        if ((s_mw[g >> 5] >> (g & 31)) & 1u)
                            bv = fmaxf(bv, __ldg(d + g));
                } else if (nib[u]) {
                    if (nib[u] & 1u) bv = fmaxf(bv, a[u].x);
                    if (nib[u] & 2u) bv = fmaxf(bv, a[u].y);
                    if (nib[u] & 4u) bv = fmaxf(bv, a[u].z);
                    if (nib[u] & 8u) bv = fmaxf(bv, a[u].w);
                }
                unsigned r = __reduce_max_sync(0xffffffffu, f2ord(bv));
                if (lane == 0 && cls[u]) s_cord[c] = r;
            }
        }
    }
    __syncthreads();

#define CHUNK_OF(G) (((G) < s) ? 0 : (((G) - s) >> 7))
#define SUPPRESSED(GI, GJ, GK, P) ({ bool _s = false;                        \
        for (int _q = 0; _q <= (P); _q++)                                    \
            if (s_pv[_q] && abs((GI) - s_pi[_q]) <= 3 &&                     \
                abs((GJ) - s_pj[_q]) <= 3 && abs((GK) - s_pk[_q]) <= 3)      \
                _s = true;                                                   \
        _s; })

    // ---- K sequential picks ----
    for (int p = 0; p < KPICK; p++) {
        // block argmax over chunk ords (tie -> lowest chunk)
        unsigned bv = 0; int bc = 0x7FFFFFFF;
        for (int c = tid; c < NC; c += NT) {
            unsigned v = s_cord[c];
            if (v > bv || (v == bv && c < bc)) { bv = v; bc = c; }
        }
#pragma unroll
        for (int o = 16; o > 0; o >>= 1) {
            unsigned ov = __shfl_down_sync(0xffffffffu, bv, o);
            int      oc = __shfl_down_sync(0xffffffffu, bc, o);
            if (ov > bv || (ov == bv && oc < bc)) { bv = ov; bc = oc; }
        }
        if (lane == 0) { s_wv[warp] = bv; s_wi[warp] = bc; }
        __syncthreads();
        if (warp == 0) {
            bv = (lane < NWARP) ? s_wv[lane] : 0;
            bc = (lane < NWARP) ? s_wi[lane] : 0x7FFFFFFF;
#pragma unroll
            for (int o = 8; o > 0; o >>= 1) {
                unsigned ov = __shfl_down_sync(0xffffffffu, bv, o);
                int      oc = __shfl_down_sync(0xffffffffu, bc, o);
                if (ov > bv || (ov == bv && oc < bc)) { bv = ov; bc = oc; }
            }
            bv = __shfl_sync(0xffffffffu, bv, 0);
            bc = __shfl_sync(0xffffffffu, bc, 0);
            // resolve first (lowest-index) voxel matching the winning value
            int base = s + (bc << 7);
            int cand = 0x7FFFFFFF;
            bool edge = (bc == 0 && s != 0) || (base + 128 > GQ);
            if (!edge) {
                int g0 = base + (lane << 2);
                int w = g0 >> 5;
                unsigned nib = __funnelshift_r(s_mw[w], s_mw[w + 1], g0) & 0xFu;
                if (nib) {
                    float4 a = __ldg(reinterpret_cast<const float4*>(d + g0));
#pragma unroll
                    for (int e = 3; e >= 0; e--) {
                        float v = (e == 0) ? a.x : (e == 1) ? a.y : (e == 2) ? a.z : a.w;
                        if ((nib >> e) & 1u) {
                            int g = g0 + e;
                            int gi = g / NXY; int rr = g - gi * NXY;
                            int gj = rr / NXQ; int gk = rr - gj * NXQ;
                            if (!SUPPRESSED(gi, gj, gk, p - 1) && f2ord(v) >= bv)
                                cand = g;
                        }
                    }
                }
            } else {
                int lo = (bc == 0) ? 0 : base;
                int hi = base + 128; if (hi > GQ) hi = GQ;
                for (int g = hi - 1 - lane; g >= lo; g -= 32) {
                    if ((s_mw[g >> 5] >> (g & 31)) & 1u) {
                        float v = __ldg(d + g);
                        int gi = g / NXY; int rr = g - gi * NXY;
                        int gj = rr / NXQ; int gk = rr - gj * NXQ;
                        if (!SUPPRESSED(gi, gj, gk, p - 1) && f2ord(v) >= bv)
                            cand = g;
                    }
                }
            }
            unsigned mg = __reduce_min_sync(0xffffffffu, (unsigned)cand);
            if (lane == 0) {
                int pidx = (mg == 0x7FFFFFFFu) ? 0 : (int)mg;
                int pi = pidx / NXY; int rr = pidx - pi * NXY;
                int pj = rr / NXQ;   int pk = rr - pj * NXQ;
                s_pi[p] = pi; s_pj[p] = pj; s_pk[p] = pk;
                s_ps[p] = ord2f(bv);
                s_pv[p] = (bv > ORD_VTH) ? 1 : 0;
            }
        }
        __syncthreads();

        // ---- NMS: flag + recompute affected chunks (value-only, suppressed) ----
        if (s_pv[p] && p < KPICK - 1) {
            const int pi = s_pi[p], pj = s_pj[p], pk = s_pk[p];
            if (tid < 49) {
                int di = tid / 7 - 3, dj = tid % 7 - 3;
                int i = pi + di, j = pj + dj;
                if (i >= 0 && i < NXQ && j >= 0 && j < NXQ) {
                    int kmin = pk - 3 < 0 ? 0 : pk - 3;
                    int kmax = pk + 3 > NXQ - 1 ? NXQ - 1 : pk + 3;
                    int ls = i * NXY + j * NXQ + kmin;
                    int le = ls + (kmax - kmin);
                    s_flag[CHUNK_OF(ls)] = 1;
                    s_flag[CHUNK_OF(le)] = 1;
                }
            }
            __syncthreads();
            int ilo = pi - 3 < 0 ? 0 : pi - 3, ihi = pi + 3 > NXQ - 1 ? NXQ - 1 : pi + 3;
            int jlo = pj - 3 < 0 ? 0 : pj - 3, jhi = pj + 3 > NXQ - 1 ? NXQ - 1 : pj + 3;
            int klo = pk - 3 < 0 ? 0 : pk - 3, khi = pk + 3 > NXQ - 1 ? NXQ - 1 : pk + 3;
            int cmin = CHUNK_OF(ilo * NXY + jlo * NXQ + klo);
            int cmax = CHUNK_OF(ihi * NXY + jhi * NXQ + khi);
            for (int c = cmin + warp; c <= cmax; c += NWARP) {
                if (!s_flag[c]) continue;                 // warp-uniform
                int base = s + (c << 7);
                float bv2 = NEGV;
                bool edge = (c == 0 && s != 0) || (base + 128 > GQ);
                if (!edge) {
                    int g0 = base + (lane << 2);
                    int w = g0 >> 5;
                    unsigned nib = __funnelshift_r(s_mw[w], s_mw[w + 1], g0) & 0xFu;
                    if (nib) {
                        float4 a = __ldg(reinterpret_cast<const float4*>(d + g0));
#pragma unroll
                        for (int e = 0; e < 4; e++) {
                            float v = (e == 0) ? a.x : (e == 1) ? a.y : (e == 2) ? a.z : a.w;
                            if ((nib >> e) & 1u) {
                                int g = g0 + e;
                                int gi = g / NXY; int rr = g - gi * NXY;
                                int gj = rr / NXQ; int gk = rr - gj * NXQ;
                                if (!SUPPRESSED(gi, gj, gk, p)) bv2 = fmaxf(bv2, v);
                            }
                        }
                    }
                } else {
                    int lo = (c == 0) ? 0 : base;
                    int hi = base + 128; if (hi > GQ) hi = GQ;
                    for (int g = lo + lane; g < hi; g += 32) {
                        if ((s_mw[g >> 5] >> (g & 31)) & 1u) {
                            float v = __ldg(d + g);
                            int gi = g / NXY; int rr = g - gi * NXY;
                            int gj = rr / NXQ; int gk = rr - gj * NXQ;
                            if (!SUPPRESSED(gi, gj, gk, p)) bv2 = fmaxf(bv2, v);
                        }
                    }
                }
                unsigned r = __reduce_max_sync(0xffffffffu, f2ord(bv2));
                if (lane == 0) { s_cord[c] = r; s_flag[c] = 0; }
            }
        }
        __syncthreads();
    }

    // ---- epilogue ----
    if (tid < KPICK) {
        int k = tid;
        int n = row / C;
        float m = node_mask[n];
        int v = s_pv[k];
        float x = 0.f, y = 0.f, z = 0.f;
        if (v) { x = s_ax[s_pi[k]]; y = s_ax[s_pj[k]]; z = s_ax[s_pk[k]]; }
        float score = v ? s_ps[k] : NEGV;
        const float* R = Rmats + (long long)n * 9;
        const float* t = tpos + (long long)n * 3;
        float gx = R[0] * x + R[1] * y + R[2] * z + t[0];
        float gy = R[3] * x + R[4] * y + R[5] * z + t[1];
        float gz = R[6] * x + R[7] * y + R[8] * z + t[2];
        long long P  = (long long)rows * KPICK;
        long long rk = (long long)row * KPICK + k;
        out[rk * 3 + 0] = x * m;
        out[rk * 3 + 1] = y * m;
        out[rk * 3 + 2] = z * m;
        out[3 * P + rk * 3 + 0] = gx * m;
        out[3 * P + rk * 3 + 1] = gy * m;
        out[3 * P + rk * 3 + 2] = gz * m;
        out[6 * P + rk] = score * m;
        out[7 * P + rk] = (v && m != 0.0f) ? 1.0f : 0.0f;
    }
}

extern "C" void kernel_launch(void* const* d_in, const int* in_sizes, int n_in,
                              void* d_out, int out_size) {
    // metadata order: density, grid_xyz, sphere_mask, coords_int, Rmats, tpos, node_mask
    const float* density   = (const float*)d_in[0];
    const float* grid_xyz  = (const float*)d_in[1];
    const float* Rmats     = (const float*)d_in[4];
    const float* tpos      = (const float*)d_in[5];
    const float* node_mask = (const float*)d_in[6];
    int rows = in_sizes[0] / GQ;   // B*N*C
    int BN   = in_sizes[6];        // B*N
    int C    = rows / BN;

    build_mask_kernel<<<(MW * 32 + 255) / 256, 256>>>(grid_xyz);
    peaks_kernel<<<rows, NT>>>(density, grid_xyz, Rmats, tpos, node_mask,
                               (float*)d_out, rows, C);
}

// round 8
// speedup vs baseline: 1.5559x; 1.5559x over previous
#include <cuda_runtime.h>
#include <cstdint>

#define NXQ 41
#define NXY 1681
#define GQ 68921
#define KPICK 4
#define NEGV (-1.0e9f)
#define VTH  (-1.0e8f)
#define NC 539               /* per-row 128-voxel chunks (shifted grid) */
#define MW 2160              /* padded 32-bit mask words */
#define MAXROWS 1024
#define PORT 8               /* portions per row in streaming kernel */
#define CPP ((NC + PORT - 1) / PORT)   /* 68 chunks per portion */
#define NT1 256
#define NWARP1 (NT1/32)
#define NT2 512
#define NWARP2 (NT2/32)

__device__ unsigned int  g_maskw[MW];
__device__ unsigned char g_class[4 * NC];       /* per (shift, chunk): 0 empty,1 partial,2 full,3 edge */
__device__ unsigned int  g_cord[MAXROWS * NC];  /* per (row, chunk) ord-max scratch */

// Order-preserving float<->uint maps
__device__ __forceinline__ unsigned f2ord(float f) {
    int u = __float_as_int(f);
    return (unsigned)(u ^ ((u >> 31) | 0x80000000));
}
__device__ __forceinline__ float ord2f(unsigned o) {
    int m = (~(int)o) >> 31;
    return __int_as_float((int)(o ^ (unsigned)(m | 0x80000000)));
}

// Sphere mask bitfield, bit-exact vs np.linalg.norm(grid_xyz) <= 6.0 in f32
// (monotone correctly-rounded sqrt => equivalent to ss <= 36.0f).
__global__ void build_mask_kernel(const float* __restrict__ grid_xyz) {
    int g = blockIdx.x * blockDim.x + threadIdx.x;
    bool inside = false;
    if (g < GQ) {
        float x = grid_xyz[3 * g + 0];
        float y = grid_xyz[3 * g + 1];
        float z = grid_xyz[3 * g + 2];
        float ss = __fadd_rn(__fadd_rn(__fmul_rn(x, x), __fmul_rn(y, y)), __fmul_rn(z, z));
        inside = (ss <= 36.0f);
    }
    unsigned int b = __ballot_sync(0xffffffffu, inside);
    if ((threadIdx.x & 31) == 0) {
        int w = g >> 5;
        if (w < MW) g_maskw[w] = b;
    }
}

__global__ void class_kernel() {
    int idx = blockIdx.x * blockDim.x + threadIdx.x;
    if (idx >= 4 * NC) return;
    int s = idx / NC, c = idx % NC;
    int base = s + (c << 7);
    unsigned char cls;
    if ((c == 0 && s != 0) || base + 128 > GQ) {
        cls = 3;
    } else {
        int w0 = base >> 5;
        unsigned o = 0, a = 0xFFFFFFFFu;
#pragma unroll
        for (int q = 0; q < 4; q++) {
            unsigned sw = __funnelshift_r(g_maskw[w0 + q], g_maskw[w0 + q + 1], s);
            o |= sw; a &= sw;
        }
        cls = (o == 0u) ? 0 : ((a == 0xFFFFFFFFu) ? 2 : 1);
    }
    g_class[idx] = cls;
}

// ---- Kernel 1: massively parallel streaming of per-chunk maxima ----
__global__ __launch_bounds__(NT1) void stream_kernel(const float* __restrict__ density) {
    const int blk  = blockIdx.x;
    const int row  = blk >> 3;          /* PORT = 8 */
    const int pr   = blk & 7;
    const int lane = threadIdx.x & 31;
    const int warp = threadIdx.x >> 5;
    const int s    = (4 - (row & 3)) & 3;
    const float* __restrict__ d = density + (long long)row * GQ;
    const unsigned ORD_NEG = f2ord(NEGV);
    const int start = pr * CPP;
    const int end   = (start + CPP < NC) ? start + CPP : NC;

    for (int cb = start + warp * 4; cb < end; cb += NWARP1 * 4) {
        unsigned nib[4]; float4 a[4]; int cls[4];
#pragma unroll
        for (int u = 0; u < 4; u++) {
            int c = cb + u;
            nib[u] = 0; cls[u] = -1;
            if (c < end) {
                cls[u] = g_class[s * NC + c];
                int g0 = s + (c << 7) + (lane << 2);
                if (cls[u] == 2) nib[u] = 0xFu;
                else if (cls[u] == 1) {
                    int w = g0 >> 5;
                    nib[u] = __funnelshift_r(__ldg(&g_maskw[w]), __ldg(&g_maskw[w + 1]), g0) & 0xFu;
                }
                if (nib[u])
                    a[u] = __ldg(reinterpret_cast<const float4*>(d + g0));
            }
        }
#pragma unroll
        for (int u = 0; u < 4; u++) {
            int c = cb + u;
            if (c >= end) break;
            if (cls[u] == 0) {
                if (lane == 0) g_cord[row * NC + c] = ORD_NEG;
                continue;
            }
            float bv = NEGV;
            if (cls[u] == 2) {
                bv = fmaxf(fmaxf(a[u].x, a[u].y), fmaxf(a[u].z, a[u].w));
            } else if (cls[u] == 3) {
                int base = s + (c << 7);
                int lo = (c == 0) ? 0 : base;
                int hi = base + 128; if (hi > GQ) hi = GQ;
                for (int g = lo + lane; g < hi; g += 32)
                    if ((__ldg(&g_maskw[g >> 5]) >> (g & 31)) & 1u)
                        bv = fmaxf(bv, __ldg(d + g));
            } else {
                if (nib[u] & 1u) bv = fmaxf(bv, a[u].x);
                if (nib[u] & 2u) bv = fmaxf(bv, a[u].y);
                if (nib[u] & 4u) bv = fmaxf(bv, a[u].z);
                if (nib[u] & 8u) bv = fmaxf(bv, a[u].w);
            }
            unsigned r = __reduce_max_sync(0xffffffffu, f2ord(bv));
            if (lane == 0) g_cord[row * NC + c] = r;
        }
    }
}

// ---- Kernel 2: picks + NMS per row (proven R4 logic, cords from scratch) ----
__global__ __launch_bounds__(NT2) void peaks_kernel(
    const float* __restrict__ density,
    const float* __restrict__ grid_xyz,
    const float* __restrict__ Rmats,
    const float* __restrict__ tpos,
    const float* __restrict__ node_mask,
    float* __restrict__ out,
    int rows, int C)
{
    __shared__ unsigned int s_mw[MW];
    __shared__ unsigned int s_cord[NC];
    __shared__ unsigned char s_flag[NC];
    __shared__ float s_ax[NXQ];
    __shared__ unsigned s_wv[NWARP2];
    __shared__ int      s_wi[NWARP2];
    __shared__ int s_pi[KPICK], s_pj[KPICK], s_pk[KPICK], s_pv[KPICK];
    __shared__ float s_ps[KPICK];

    const int tid  = threadIdx.x;
    const int lane = tid & 31;
    const int warp = tid >> 5;
    const int row  = blockIdx.x;
    const int s    = (4 - (row & 3)) & 3;
    const float* __restrict__ d = density + (long long)row * GQ;
    const unsigned ORD_VTH = f2ord(VTH);

    for (int i = tid; i < MW; i += NT2) s_mw[i] = g_maskw[i];
    for (int c = tid; c < NC; c += NT2) { s_cord[c] = g_cord[row * NC + c]; s_flag[c] = 0; }
    if (tid < NXQ) s_ax[tid] = grid_xyz[(long long)tid * NXY * 3];
    __syncthreads();

#define CHUNK_OF(G) (((G) < s) ? 0 : (((G) - s) >> 7))
#define SUPPRESSED(GI, GJ, GK, P) ({ bool _s = false;                        \
        for (int _q = 0; _q <= (P); _q++)                                    \
            if (s_pv[_q] && abs((GI) - s_pi[_q]) <= 3 &&                     \
                abs((GJ) - s_pj[_q]) <= 3 && abs((GK) - s_pk[_q]) <= 3)      \
                _s = true;                                                   \
        _s; })

    for (int p = 0; p < KPICK; p++) {
        unsigned bv = 0; int bc = 0x7FFFFFFF;
        for (int c = tid; c < NC; c += NT2) {
            unsigned v = s_cord[c];
            if (v > bv || (v == bv && c < bc)) { bv = v; bc = c; }
        }
#pragma unroll
        for (int o = 16; o > 0; o >>= 1) {
            unsigned ov = __shfl_down_sync(0xffffffffu, bv, o);
            int      oc = __shfl_down_sync(0xffffffffu, bc, o);
            if (ov > bv || (ov == bv && oc < bc)) { bv = ov; bc = oc; }
        }
        if (lane == 0) { s_wv[warp] = bv; s_wi[warp] = bc; }
        __syncthreads();
        if (warp == 0) {
            bv = (lane < NWARP2) ? s_wv[lane] : 0;
            bc = (lane < NWARP2) ? s_wi[lane] : 0x7FFFFFFF;
#pragma unroll
            for (int o = 8; o > 0; o >>= 1) {
                unsigned ov = __shfl_down_sync(0xffffffffu, bv, o);
                int      oc = __shfl_down_sync(0xffffffffu, bc, o);
                if (ov > bv || (ov == bv && oc < bc)) { bv = ov; bc = oc; }
            }
            bv = __shfl_sync(0xffffffffu, bv, 0);
            bc = __shfl_sync(0xffffffffu, bc, 0);
            // resolve first (lowest-index) voxel matching the winning value
            int base = s + (bc << 7);
            int cand = 0x7FFFFFFF;
            bool edge = (bc == 0 && s != 0) || (base + 128 > GQ);
            if (!edge) {
                int g0 = base + (lane << 2);
                int w = g0 >> 5;
                unsigned nib = __funnelshift_r(s_mw[w], s_mw[w + 1], g0) & 0xFu;
                if (nib) {
                    float4 a = __ldg(reinterpret_cast<const float4*>(d + g0));
#pragma unroll
                    for (int e = 3; e >= 0; e--) {
                        float v = (e == 0) ? a.x : (e == 1) ? a.y : (e == 2) ? a.z : a.w;
                        if ((nib >> e) & 1u) {
                            int g = g0 + e;
                            int gi = g / NXY; int rr = g - gi * NXY;
                            int gj = rr / NXQ; int gk = rr - gj * NXQ;
                            if (!SUPPRESSED(gi, gj, gk, p - 1) && f2ord(v) >= bv)
                                cand = g;
                        }
                    }
                }
            } else {
                int lo = (bc == 0) ? 0 : base;
                int hi = base + 128; if (hi > GQ) hi = GQ;
                for (int g = hi - 1 - lane; g >= lo; g -= 32) {
                    if ((s_mw[g >> 5] >> (g & 31)) & 1u) {
                        float v = __ldg(d + g);
                        int gi = g / NXY; int rr = g - gi * NXY;
                        int gj = rr / NXQ; int gk = rr - gj * NXQ;
                        if (!SUPPRESSED(gi, gj, gk, p - 1) && f2ord(v) >= bv)
                            cand = g;
                    }
                }
            }
            unsigned mg = __reduce_min_sync(0xffffffffu, (unsigned)cand);
            if (lane == 0) {
                int pidx = (mg == 0x7FFFFFFFu) ? 0 : (int)mg;
                int pi = pidx / NXY; int rr = pidx - pi * NXY;
                int pj = rr / NXQ;   int pk = rr - pj * NXQ;
                s_pi[p] = pi; s_pj[p] = pj; s_pk[p] = pk;
                s_ps[p] = ord2f(bv);
                s_pv[p] = (bv > ORD_VTH) ? 1 : 0;
            }
        }
        __syncthreads();

        if (s_pv[p] && p < KPICK - 1) {
            const int pi = s_pi[p], pj = s_pj[p], pk = s_pk[p];
            if (tid < 49) {
                int di = tid / 7 - 3, dj = tid % 7 - 3;
                int i = pi + di, j = pj + dj;
                if (i >= 0 && i < NXQ && j >= 0 && j < NXQ) {
                    int kmin = pk - 3 < 0 ? 0 : pk - 3;
                    int kmax = pk + 3 > NXQ - 1 ? NXQ - 1 : pk + 3;
                    int ls = i * NXY + j * NXQ + kmin;
                    int le = ls + (kmax - kmin);
                    s_flag[CHUNK_OF(ls)] = 1;
                    s_flag[CHUNK_OF(le)] = 1;
                }
            }
            __syncthreads();
            int ilo = pi - 3 < 0 ? 0 : pi - 3, ihi = pi + 3 > NXQ - 1 ? NXQ - 1 : pi + 3;
            int jlo = pj - 3 < 0 ? 0 : pj - 3, jhi = pj + 3 > NXQ - 1 ? NXQ - 1 : pj + 3;
            int klo = pk - 3 < 0 ? 0 : pk - 3, khi = pk + 3 > NXQ - 1 ? NXQ - 1 : pk + 3;
            int cmin = CHUNK_OF(ilo * NXY + jlo * NXQ + klo);
            int cmax = CHUNK_OF(ihi * NXY + jhi * NXQ + khi);
            for (int c = cmin + warp; c <= cmax; c += NWARP2) {
                if (!s_flag[c]) continue;
                int base = s + (c << 7);
                float bv2 = NEGV;
                bool edge = (c == 0 && s != 0) || (base + 128 > GQ);
                if (!edge) {
                    int g0 = base + (lane << 2);
                    int w = g0 >> 5;
                    unsigned nib = __funnelshift_r(s_mw[w], s_mw[w + 1], g0) & 0xFu;
                    if (nib) {
                        float4 a = __ldg(reinterpret_cast<const float4*>(d + g0));
#pragma unroll
                        for (int e = 0; e < 4; e++) {
                            float v = (e == 0) ? a.x : (e == 1) ? a.y : (e == 2) ? a.z : a.w;
                            if ((nib >> e) & 1u) {
                                int g = g0 + e;
                                int gi = g / NXY; int rr = g - gi * NXY;
                                int gj = rr / NXQ; int gk = rr - gj * NXQ;
                                if (!SUPPRESSED(gi, gj, gk, p)) bv2 = fmaxf(bv2, v);
                            }
                        }
                    }
                } else {
                    int lo = (c == 0) ? 0 : base;
                    int hi = base + 128; if (hi > GQ) hi = GQ;
                    for (int g = lo + lane; g < hi; g += 32) {
                        if ((s_mw[g >> 5] >> (g & 31)) & 1u) {
                            float v = __ldg(d + g);
                            int gi = g / NXY; int rr = g - gi * NXY;
                            int gj = rr / NXQ; int gk = rr - gj * NXQ;
                            if (!SUPPRESSED(gi, gj, gk, p)) bv2 = fmaxf(bv2, v);
                        }
                    }
                }
                unsigned r = __reduce_max_sync(0xffffffffu, f2ord(bv2));
                if (lane == 0) { s_cord[c] = r; s_flag[c] = 0; }
            }
        }
        __syncthreads();
    }

    // ---- epilogue ----
    if (tid < KPICK) {
        int k = tid;
        int n = row / C;
        float m = node_mask[n];
        int v = s_pv[k];
        float x = 0.f, y = 0.f, z = 0.f;
        if (v) { x = s_ax[s_pi[k]]; y = s_ax[s_pj[k]]; z = s_ax[s_pk[k]]; }
        float score = v ? s_ps[k] : NEGV;
        const float* R = Rmats + (long long)n * 9;
        const float* t = tpos + (long long)n * 3;
        float gx = R[0] * x + R[1] * y + R[2] * z + t[0];
        float gy = R[3] * x + R[4] * y + R[5] * z + t[1];
        float gz = R[6] * x + R[7] * y + R[8] * z + t[2];
        long long P  = (long long)rows * KPICK;
        long long rk = (long long)row * KPICK + k;
        out[rk * 3 + 0] = x * m;
        out[rk * 3 + 1] = y * m;
        out[rk * 3 + 2] = z * m;
        out[3 * P + rk * 3 + 0] = gx * m;
        out[3 * P + rk * 3 + 1] = gy * m;
        out[3 * P + rk * 3 + 2] = gz * m;
        out[6 * P + rk] = score * m;
        out[7 * P + rk] = (v && m != 0.0f) ? 1.0f : 0.0f;
    }
}

extern "C" void kernel_launch(void* const* d_in, const int* in_sizes, int n_in,
                              void* d_out, int out_size) {
    // metadata order: density, grid_xyz, sphere_mask, coords_int, Rmats, tpos, node_mask
    const float* density   = (const float*)d_in[0];
    const float* grid_xyz  = (const float*)d_in[1];
    const float* Rmats     = (const float*)d_in[4];
    const float* tpos      = (const float*)d_in[5];
    const float* node_mask = (const float*)d_in[6];
    int rows = in_sizes[0] / GQ;   // B*N*C
    int BN   = in_sizes[6];        // B*N
    int C    = rows / BN;
    if (rows > MAXROWS) rows = MAXROWS;

    build_mask_kernel<<<(MW * 32 + 255) / 256, 256>>>(grid_xyz);
    class_kernel<<<(4 * NC + 255) / 256, 256>>>();
    stream_kernel<<<rows * PORT, NT1>>>(density);
    peaks_kernel<<<rows, NT2>>>(density, grid_xyz, Rmats, tpos, node_mask,
                                (float*)d_out, rows, C);
}